// round 16
// baseline (speedup 1.0000x reference)
#include <cuda_runtime.h>
#include <cuda_fp16.h>
#include <math.h>
#include <stdint.h>

// Problem constants
#define BATCH      8192
#define INPUT_DIM  256
#define HIDDEN     64
#define NUM_INNER  255
#define NUM_LEAVES 256
#define DEPTH      8

#define NODES_PAD  256
#define NX   (BATCH * INPUT_DIM)
#define NW1  (NUM_INNER * HIDDEN * INPUT_DIM)
#define NW1P (NODES_PAD * HIDDEN * INPUT_DIM)

// GEMM tiling: CTA = 128 rows x 128 cols (2 nodes), K in BK=32 stages
#define BM 128
#define BN 128
#define BK 32
#define NSTAGES (INPUT_DIM / BK)   // 8
#define NPIPE 4

// fp16 operand scratch + transposed node-output scratch (no allocation)
__device__ __half g_xh[NX];
__device__ __half g_w1h[NW1P];
__device__ float  g_no[NODES_PAD * BATCH];   // [node][batch], coalesced stores

// ---------------------------------------------------------------------------
// Prep: fp32 -> fp16 over a flat chunk space (16B output chunks).
// grid 1536 x 256 = 393216 threads = TOTCH/2: one loop-free iteration of
// 2 independent chunks per thread.
// ---------------------------------------------------------------------------
#define XCH (NX / 8)          // 262144
#define WCH (NW1P / 8)        // 524288
#define TOTCH (XCH + WCH)     // 786432
#define PREP_NTH (TOTCH / 2)  // 393216 = 1536 * 256

__device__ __forceinline__ uint4 prep_cvt(int i, const float4* __restrict__ xv,
                                          const float4* __restrict__ wv) {
    float4 a, b;
    if (i < XCH) {
        a = xv[2 * i]; b = xv[2 * i + 1];
    } else {
        int j = i - XCH;
        if (j < NW1 / 8) { a = wv[2 * j]; b = wv[2 * j + 1]; }
        else { a = make_float4(0.f, 0.f, 0.f, 0.f); b = a; }
    }
    __half2 h0 = __floats2half2_rn(a.x, a.y);
    __half2 h1 = __floats2half2_rn(a.z, a.w);
    __half2 h2 = __floats2half2_rn(b.x, b.y);
    __half2 h3 = __floats2half2_rn(b.z, b.w);
    uint4 o;
    o.x = *(uint32_t*)&h0; o.y = *(uint32_t*)&h1;
    o.z = *(uint32_t*)&h2; o.w = *(uint32_t*)&h3;
    return o;
}

__device__ __forceinline__ void prep_put(int i, uint4 o) {
    if (i < XCH) ((uint4*)g_xh)[i] = o;
    else         ((uint4*)g_w1h)[i - XCH] = o;
}

__global__ void sdt_prep_kernel(const float* __restrict__ x,
                                const float* __restrict__ w1) {
    const int i = blockIdx.x * blockDim.x + threadIdx.x;
    const float4* xv = (const float4*)x;
    const float4* wv = (const float4*)w1;
    uint4 o0 = prep_cvt(i, xv, wv);
    uint4 o1 = prep_cvt(i + PREP_NTH, xv, wv);
    prep_put(i, o0);
    prep_put(i + PREP_NTH, o1);
}

// ---------------------------------------------------------------------------
// smem: 4 stage buffers of (A 8KB | B 8KB), then 1KB b1/w2 epilogue staging.
// Rows 64B (32 halves); 16B chunk c stored at c ^ ((row>>1)&3).
// ---------------------------------------------------------------------------
#define OFF_A 0
#define OFF_B 8192
#define BUF_STRIDE 16384
#define OFF_EPI (NPIPE * BUF_STRIDE)      // 65536: b1s (512B) | w2s (512B)
#define SMEM_TOTAL (OFF_EPI + 1024)       // 66560

__device__ __forceinline__ void cp_async16(uint32_t saddr, const void* gaddr) {
    asm volatile("cp.async.cg.shared.global [%0], [%1], 16;\n"
                 :: "r"(saddr), "l"(gaddr) : "memory");
}
__device__ __forceinline__ void cp_commit() {
    asm volatile("cp.async.commit_group;\n" ::: "memory");
}
__device__ __forceinline__ void cp_wait2() {
    asm volatile("cp.async.wait_group 2;\n" ::: "memory");
}
__device__ __forceinline__ void ldsm_x4(uint32_t* r, uint32_t addr) {
    asm volatile("ldmatrix.sync.aligned.m8n8.x4.shared.b16 {%0,%1,%2,%3}, [%4];\n"
                 : "=r"(r[0]), "=r"(r[1]), "=r"(r[2]), "=r"(r[3])
                 : "r"(addr));
}
__device__ __forceinline__ void mma_fp16(float* c, const uint32_t* a, const uint32_t* b) {
    asm volatile(
        "mma.sync.aligned.m16n8k16.row.col.f32.f16.f16.f32 "
        "{%0,%1,%2,%3}, {%4,%5,%6,%7}, {%8,%9}, {%0,%1,%2,%3};\n"
        : "+f"(c[0]), "+f"(c[1]), "+f"(c[2]), "+f"(c[3])
        : "r"(a[0]), "r"(a[1]), "r"(a[2]), "r"(a[3]), "r"(b[0]), "r"(b[1]));
}

// ---------------------------------------------------------------------------
// Kernel 1: fused node-MLP GEMM (fp16 operands, fp32 accum).
// Identical to the proven round-8/15 kernel except the epilogue stores go to
// the TRANSPOSED scratch g_no[node][batch]: the 8 writing lanes per (mt,h)
// cover consecutive rows -> 32B-contiguous stores (8x fewer write sectors
// than the strided [BATCH,255] layout).
// ---------------------------------------------------------------------------
__global__ __launch_bounds__(256, 2)
void sdt_mma_kernel(const float* __restrict__ b1,
                    const float* __restrict__ w2,
                    const float* __restrict__ b2) {
    extern __shared__ char smem[];
    const uint32_t smem_base = (uint32_t)__cvta_generic_to_shared(smem);

    const int tid   = threadIdx.x;
    const int lane  = tid & 31;
    const int warp  = tid >> 5;
    const int wm    = warp & 3;        // 32-row slice
    const int wn    = warp >> 2;       // 0..1 -> which node (64 cols)
    const int mbase = blockIdx.y * BM;
    const int nbase = blockIdx.x * BN; // padded w1 row (node*64 + h)

    float acc[2][8][4];
#pragma unroll
    for (int mt = 0; mt < 2; mt++)
#pragma unroll
        for (int nt = 0; nt < 8; nt++)
#pragma unroll
            for (int e = 0; e < 4; e++) acc[mt][nt][e] = 0.0f;

    const int rA0 = tid >> 2, cA0 = tid & 3;
    const uint32_t swA0 = rA0 * 64 + (cA0 ^ ((rA0 >> 1) & 3)) * 16;
    const int rA1 = (tid + 256) >> 2, cA1 = tid & 3;
    const uint32_t swA1 = rA1 * 64 + (cA1 ^ ((rA1 >> 1) & 3)) * 16;

    auto issue_loads = [&](int st) {
        const int k0 = st * BK;
        const uint32_t base = smem_base + (st & (NPIPE - 1)) * BUF_STRIDE;
        cp_async16(base + OFF_A + swA0,
                   g_xh + (size_t)(mbase + rA0) * INPUT_DIM + k0 + cA0 * 8);
        cp_async16(base + OFF_A + swA1,
                   g_xh + (size_t)(mbase + rA1) * INPUT_DIM + k0 + cA1 * 8);
        cp_async16(base + OFF_B + swA0,
                   g_w1h + (size_t)(nbase + rA0) * INPUT_DIM + k0 + cA0 * 8);
        cp_async16(base + OFF_B + swA1,
                   g_w1h + (size_t)(nbase + rA1) * INPUT_DIM + k0 + cA1 * 8);
    };

    // Prologue: stage 0 + b1/w2 epilogue staging in commit-group 0.
    issue_loads(0);
    if (tid < 64) {
        const int half = tid >> 5;             // 0 = b1, 1 = w2
        const int ch5  = tid & 31;
        const int g    = blockIdx.x * 2 * HIDDEN + ch5 * 4;
        if (g + 4 <= NUM_INNER * HIDDEN) {
            const float* src = half ? w2 : b1;
            cp_async16(smem_base + OFF_EPI + half * 512 + ch5 * 16, src + g);
        }
    }
    cp_commit();
    issue_loads(1); cp_commit();
    issue_loads(2); cp_commit();

    for (int st = 0; st < NSTAGES; st++) {
        cp_wait2();
        __syncthreads();

        const uint32_t base = smem_base + (st & (NPIPE - 1)) * BUF_STRIDE;
#pragma unroll
        for (int s = 0; s < 2; s++) {
            uint32_t ah[2][4];
#pragma unroll
            for (int mt = 0; mt < 2; mt++) {
                int row   = wm * 32 + mt * 16 + (lane & 15);
                int chunk = 2 * s + (lane >> 4);
                int sw    = chunk ^ ((row >> 1) & 3);
                ldsm_x4(ah[mt], base + OFF_A + row * 64 + sw * 16);
            }
#pragma unroll
            for (int nt2 = 0; nt2 < 4; nt2++) {
                int row   = wn * 64 + nt2 * 16 + (lane & 7) + ((lane >> 4) << 3);
                int chunk = 2 * s + ((lane >> 3) & 1);
                int sw    = chunk ^ ((row >> 1) & 3);
                uint32_t bh[4];
                ldsm_x4(bh, base + OFF_B + row * 64 + sw * 16);
#pragma unroll
                for (int mt = 0; mt < 2; mt++) {
#pragma unroll
                    for (int j = 0; j < 2; j++)
                        mma_fp16(acc[mt][nt2 * 2 + j], ah[mt], bh + j * 2);
                }
            }
        }
        if (st + 3 < NSTAGES) issue_loads(st + 3);
        cp_commit();
    }

    // ---- Fused epilogue: bias -> relu -> dot w2 -> sigmoid -> g_no (T) ----
    const int node = blockIdx.x * 2 + wn;
    if (node < NUM_INNER) {
        const float* b1s = (const float*)(smem + OFF_EPI);
        const float* w2s = (const float*)(smem + OFF_EPI + 512);
        float b1v[16], w2v[16];
#pragma unroll
        for (int t = 0; t < 8; t++) {
#pragma unroll
            for (int e = 0; e < 2; e++) {
                int col = t * 8 + (lane & 3) * 2 + e;
                b1v[t * 2 + e] = b1s[wn * HIDDEN + col];
                w2v[t * 2 + e] = w2s[wn * HIDDEN + col];
            }
        }
        const float b2v = b2[node];
        float* no_node = g_no + (size_t)node * BATCH;
#pragma unroll
        for (int mt = 0; mt < 2; mt++) {
#pragma unroll
            for (int h = 0; h < 2; h++) {
                float sum = 0.0f;
#pragma unroll
                for (int t = 0; t < 8; t++) {
#pragma unroll
                    for (int e = 0; e < 2; e++) {
                        float v = acc[mt][t][h * 2 + e] + b1v[t * 2 + e];
                        v = fmaxf(v, 0.0f);
                        sum = fmaf(v, w2v[t * 2 + e], sum);
                    }
                }
                sum += __shfl_xor_sync(0xffffffffu, sum, 1);
                sum += __shfl_xor_sync(0xffffffffu, sum, 2);
                if ((lane & 3) == 0) {
                    int row = mbase + wm * 32 + mt * 16 + (lane >> 2) + h * 8;
                    float lg = sum + b2v;
                    float sg = 1.0f / (1.0f + __expf(-lg));
                    no_node[row] = sg;     // consecutive rows -> 32B-contig
                }
            }
        }
    }
}

// ---------------------------------------------------------------------------
// Kernel 2: tree traversal, 16 rows per block. Reads the transposed scratch
// (thread t loads its 16 rows as 4 x float4, 64B contiguous) and takes over
// writing node_out in the required [BATCH,255] layout, where threads
// t = 0..254 are naturally coalesced per row.
// ---------------------------------------------------------------------------
#define RPB 16
__global__ __launch_bounds__(256)
void sdt_tree_kernel(const float* __restrict__ leaf,
                     float* __restrict__ h_out,
                     float* __restrict__ path_out,
                     float* __restrict__ node_out,
                     float* __restrict__ reach_out) {
    const int b0 = blockIdx.x * RPB;
    const int t  = threadIdx.x;

    __shared__ float p[RPB][NUM_INNER];
    __shared__ float red[RPB][8];

    if (t < NUM_INNER) {
        const float4* src = (const float4*)(g_no + (size_t)t * BATCH + b0);
        float v[RPB];
#pragma unroll
        for (int q = 0; q < RPB / 4; q++) {
            float4 f = src[q];
            v[q * 4 + 0] = f.x; v[q * 4 + 1] = f.y;
            v[q * 4 + 2] = f.z; v[q * 4 + 3] = f.w;
        }
#pragma unroll
        for (int r = 0; r < RPB; r++) {
            p[r][t] = v[r];
            node_out[(size_t)(b0 + r) * NUM_INNER + t] = v[r];  // coalesced
        }
    }
    __syncthreads();

    float prob[RPB];
#pragma unroll
    for (int r = 0; r < RPB; r++) prob[r] = 1.0f;

    int n = 0;
#pragma unroll
    for (int v = 0; v < DEPTH; v++) {
        if ((t & ((1 << (DEPTH - v)) - 1)) == 0) {
#pragma unroll
            for (int r = 0; r < RPB; r++)
                reach_out[(size_t)(b0 + r) * NUM_INNER + n] = prob[r];
        }
        int bit = (t >> (DEPTH - 1 - v)) & 1;
#pragma unroll
        for (int r = 0; r < RPB; r++) {
            float pv = p[r][n];
            prob[r] *= bit ? pv : (1.0f - pv);
        }
        n = 2 * n + 1 + bit;
    }

    const float lf = leaf[t];
#pragma unroll
    for (int r = 0; r < RPB; r++) {
        path_out[(size_t)(b0 + r) * NUM_LEAVES + t] = prob[r];
        float c = prob[r] * lf;
#pragma unroll
        for (int off = 16; off; off >>= 1)
            c += __shfl_xor_sync(0xffffffffu, c, off);
        if ((t & 31) == 0) red[r][t >> 5] = c;
    }
    __syncthreads();
    if (t < 128) {
        int r = t >> 3, i = t & 7;
        float v = red[r][i];
        v += __shfl_xor_sync(0xffffffffu, v, 4);
        v += __shfl_xor_sync(0xffffffffu, v, 2);
        v += __shfl_xor_sync(0xffffffffu, v, 1);
        if (i == 0) h_out[b0 + r] = v;
    }
}

// ---------------------------------------------------------------------------
// Launch. d_in: x, w1, b1, w2, b2, leaf.
// d_out: [h_out | path_probs | node_outputs | node_reach]
// ---------------------------------------------------------------------------
extern "C" void kernel_launch(void* const* d_in, const int* in_sizes, int n_in,
                              void* d_out, int out_size) {
    const float* x    = (const float*)d_in[0];
    const float* w1   = (const float*)d_in[1];
    const float* b1   = (const float*)d_in[2];
    const float* w2   = (const float*)d_in[3];
    const float* b2   = (const float*)d_in[4];
    const float* leaf = (const float*)d_in[5];

    float* out       = (float*)d_out;
    float* h_out     = out;
    float* path_out  = out + BATCH;
    float* node_out  = out + BATCH + (size_t)BATCH * NUM_LEAVES;
    float* reach_out = node_out + (size_t)BATCH * NUM_INNER;

    sdt_prep_kernel<<<1536, 256>>>(x, w1);

    cudaFuncSetAttribute(sdt_mma_kernel,
                         cudaFuncAttributeMaxDynamicSharedMemorySize, SMEM_TOTAL);
    dim3 grid(NODES_PAD / 2, BATCH / BM);   // 128 x 64
    sdt_mma_kernel<<<grid, 256, SMEM_TOTAL>>>(b1, w2, b2);

    sdt_tree_kernel<<<BATCH / RPB, 256>>>(leaf, h_out, path_out, node_out, reach_out);
}

// round 17
// speedup vs baseline: 1.0265x; 1.0265x over previous
#include <cuda_runtime.h>
#include <cuda_fp16.h>
#include <math.h>
#include <stdint.h>

// Problem constants
#define BATCH      8192
#define INPUT_DIM  256
#define HIDDEN     64
#define NUM_INNER  255
#define NUM_LEAVES 256
#define DEPTH      8

#define NODES_PAD  256
#define NX   (BATCH * INPUT_DIM)
#define NW1  (NUM_INNER * HIDDEN * INPUT_DIM)
#define NW1P (NODES_PAD * HIDDEN * INPUT_DIM)

// GEMM tiling: CTA = 128 rows x 128 cols (2 nodes), K in BK=32 stages
#define BM 128
#define BN 128
#define BK 32
#define NSTAGES (INPUT_DIM / BK)   // 8
#define NPIPE 4

// fp16 operand scratch (static device arrays; no allocation)
__device__ __half g_xh[NX];
__device__ __half g_w1h[NW1P];

// ---------------------------------------------------------------------------
// Prep: fp32 -> fp16, vectorized 8 elems/iter. Zero-pads w1 beyond NW1.
// ---------------------------------------------------------------------------
__global__ void sdt_prep_kernel(const float* __restrict__ x,
                                const float* __restrict__ w1) {
    const int tid = blockIdx.x * blockDim.x + threadIdx.x;
    const int nth = gridDim.x * blockDim.x;
    const float4* xv  = (const float4*)x;
    const float4* wv  = (const float4*)w1;
    uint4* xo = (uint4*)g_xh;
    uint4* wo = (uint4*)g_w1h;

    for (int i = tid; i < NX / 8; i += nth) {
        float4 a = xv[2 * i], b = xv[2 * i + 1];
        __half2 h0 = __floats2half2_rn(a.x, a.y);
        __half2 h1 = __floats2half2_rn(a.z, a.w);
        __half2 h2 = __floats2half2_rn(b.x, b.y);
        __half2 h3 = __floats2half2_rn(b.z, b.w);
        uint4 o;
        o.x = *(uint32_t*)&h0; o.y = *(uint32_t*)&h1;
        o.z = *(uint32_t*)&h2; o.w = *(uint32_t*)&h3;
        xo[i] = o;
    }
    for (int i = tid; i < NW1P / 8; i += nth) {
        uint4 o;
        if (i < NW1 / 8) {
            float4 a = wv[2 * i], b = wv[2 * i + 1];
            __half2 h0 = __floats2half2_rn(a.x, a.y);
            __half2 h1 = __floats2half2_rn(a.z, a.w);
            __half2 h2 = __floats2half2_rn(b.x, b.y);
            __half2 h3 = __floats2half2_rn(b.z, b.w);
            o.x = *(uint32_t*)&h0; o.y = *(uint32_t*)&h1;
            o.z = *(uint32_t*)&h2; o.w = *(uint32_t*)&h3;
        } else {
            o.x = o.y = o.z = o.w = 0u;
        }
        wo[i] = o;
    }
}

// ---------------------------------------------------------------------------
// smem: 4 stage buffers of (A 8KB | B 8KB). Rows 64B (32 halves);
// 16B chunk c stored at c ^ ((row>>1)&3).
// ---------------------------------------------------------------------------
#define OFF_A 0
#define OFF_B 8192
#define BUF_STRIDE 16384
#define SMEM_TOTAL (NPIPE * BUF_STRIDE)   // 65536

__device__ __forceinline__ void cp_async16(uint32_t saddr, const void* gaddr) {
    asm volatile("cp.async.cg.shared.global [%0], [%1], 16;\n"
                 :: "r"(saddr), "l"(gaddr) : "memory");
}
__device__ __forceinline__ void cp_commit() {
    asm volatile("cp.async.commit_group;\n" ::: "memory");
}
__device__ __forceinline__ void cp_wait2() {
    asm volatile("cp.async.wait_group 2;\n" ::: "memory");
}
__device__ __forceinline__ void ldsm_x4(uint32_t* r, uint32_t addr) {
    asm volatile("ldmatrix.sync.aligned.m8n8.x4.shared.b16 {%0,%1,%2,%3}, [%4];\n"
                 : "=r"(r[0]), "=r"(r[1]), "=r"(r[2]), "=r"(r[3])
                 : "r"(addr));
}
__device__ __forceinline__ void mma_fp16(float* c, const uint32_t* a, const uint32_t* b) {
    asm volatile(
        "mma.sync.aligned.m16n8k16.row.col.f32.f16.f16.f32 "
        "{%0,%1,%2,%3}, {%4,%5,%6,%7}, {%8,%9}, {%0,%1,%2,%3};\n"
        : "+f"(c[0]), "+f"(c[1]), "+f"(c[2]), "+f"(c[3])
        : "r"(a[0]), "r"(a[1]), "r"(a[2]), "r"(a[3]), "r"(b[0]), "r"(b[1]));
}

// ---------------------------------------------------------------------------
// Kernel 1: fused node-MLP GEMM (fp16 operands, fp32 accum).
// Grid: x = 128 node-tiles (2 nodes each), y = 64 batch-tiles.
// 256 threads = 8 warps: wm = warp&3 (32-row slice), wn = warp>>2 (node).
// Warp tile 32m x 64n -> acc[2][8][4] = 64 regs. 2 CTAs/SM.
// Single barrier per stage: wait -> sync -> compute(st) -> issue(st+3) ->
// commit. issue(st+3) writes buf (st-1)%4, whose readers (compute st-1) all
// passed this iteration's barrier; a (possibly empty) commit every iteration
// keeps wait_group 2 exact for all stages.
// ---------------------------------------------------------------------------
__global__ __launch_bounds__(256, 2)
void sdt_mma_kernel(const float* __restrict__ b1,
                    const float* __restrict__ w2,
                    const float* __restrict__ b2,
                    float* __restrict__ node_out /* [BATCH, 255] */) {
    extern __shared__ char smem[];
    const uint32_t smem_base = (uint32_t)__cvta_generic_to_shared(smem);

    const int tid   = threadIdx.x;
    const int lane  = tid & 31;
    const int warp  = tid >> 5;
    const int wm    = warp & 3;        // 32-row slice
    const int wn    = warp >> 2;       // 0..1 -> which node (64 cols)
    const int mbase = blockIdx.y * BM;
    const int nbase = blockIdx.x * BN; // padded w1 row (node*64 + h)

    float acc[2][8][4];
#pragma unroll
    for (int mt = 0; mt < 2; mt++)
#pragma unroll
        for (int nt = 0; nt < 8; nt++)
#pragma unroll
            for (int e = 0; e < 4; e++) acc[mt][nt][e] = 0.0f;

    // Per-thread swizzled smem offsets (constant across stages).
    const int rA0 = tid >> 2, cA0 = tid & 3;
    const uint32_t swA0 = rA0 * 64 + (cA0 ^ ((rA0 >> 1) & 3)) * 16;
    const int rA1 = (tid + 256) >> 2, cA1 = tid & 3;
    const uint32_t swA1 = rA1 * 64 + (cA1 ^ ((rA1 >> 1) & 3)) * 16;

    auto issue_loads = [&](int st) {
        const int k0 = st * BK;
        const uint32_t base = smem_base + (st & (NPIPE - 1)) * BUF_STRIDE;
        cp_async16(base + OFF_A + swA0,
                   g_xh + (size_t)(mbase + rA0) * INPUT_DIM + k0 + cA0 * 8);
        cp_async16(base + OFF_A + swA1,
                   g_xh + (size_t)(mbase + rA1) * INPUT_DIM + k0 + cA1 * 8);
        cp_async16(base + OFF_B + swA0,
                   g_w1h + (size_t)(nbase + rA0) * INPUT_DIM + k0 + cA0 * 8);
        cp_async16(base + OFF_B + swA1,
                   g_w1h + (size_t)(nbase + rA1) * INPUT_DIM + k0 + cA1 * 8);
    };

    // Prologue: 3 stages in flight.
    issue_loads(0); cp_commit();
    issue_loads(1); cp_commit();
    issue_loads(2); cp_commit();

    for (int st = 0; st < NSTAGES; st++) {
        cp_wait2();            // groups committed = 3+st; <=2 pending -> st done
        __syncthreads();

        const uint32_t base = smem_base + (st & (NPIPE - 1)) * BUF_STRIDE;
#pragma unroll
        for (int s = 0; s < 2; s++) {       // two k16 steps per stage
            uint32_t ah[2][4];
#pragma unroll
            for (int mt = 0; mt < 2; mt++) {
                int row   = wm * 32 + mt * 16 + (lane & 15);
                int chunk = 2 * s + (lane >> 4);
                int sw    = chunk ^ ((row >> 1) & 3);
                ldsm_x4(ah[mt], base + OFF_A + row * 64 + sw * 16);
            }
#pragma unroll
            for (int nt2 = 0; nt2 < 4; nt2++) {
                int row   = wn * 64 + nt2 * 16 + (lane & 7) + ((lane >> 4) << 3);
                int chunk = 2 * s + ((lane >> 3) & 1);
                int sw    = chunk ^ ((row >> 1) & 3);
                uint32_t bh[4];
                ldsm_x4(bh, base + OFF_B + row * 64 + sw * 16);
#pragma unroll
                for (int mt = 0; mt < 2; mt++) {
#pragma unroll
                    for (int j = 0; j < 2; j++)
                        mma_fp16(acc[mt][nt2 * 2 + j], ah[mt], bh + j * 2);
                }
            }
        }
        if (st + 3 < NSTAGES) issue_loads(st + 3);
        cp_commit();           // commit every iteration (may be empty)
    }

    // ---- Fused epilogue: bias -> relu -> dot w2 -> sigmoid -> node_out ----
    const int node = blockIdx.x * 2 + wn;
    if (node < NUM_INNER) {
        float b1v[16], w2v[16];
#pragma unroll
        for (int t = 0; t < 8; t++) {
#pragma unroll
            for (int e = 0; e < 2; e++) {
                int col = t * 8 + (lane & 3) * 2 + e;
                b1v[t * 2 + e] = b1[node * HIDDEN + col];
                w2v[t * 2 + e] = w2[node * HIDDEN + col];
            }
        }
        const float b2v = b2[node];
#pragma unroll
        for (int mt = 0; mt < 2; mt++) {
#pragma unroll
            for (int h = 0; h < 2; h++) {
                float sum = 0.0f;
#pragma unroll
                for (int t = 0; t < 8; t++) {
#pragma unroll
                    for (int e = 0; e < 2; e++) {
                        float v = acc[mt][t][h * 2 + e] + b1v[t * 2 + e];
                        v = fmaxf(v, 0.0f);
                        sum = fmaf(v, w2v[t * 2 + e], sum);
                    }
                }
                sum += __shfl_xor_sync(0xffffffffu, sum, 1);
                sum += __shfl_xor_sync(0xffffffffu, sum, 2);
                if ((lane & 3) == 0) {
                    int row = mbase + wm * 32 + mt * 16 + (lane >> 2) + h * 8;
                    float lg = sum + b2v;
                    float sg = 1.0f / (1.0f + __expf(-lg));
                    node_out[(size_t)row * NUM_INNER + node] = sg;
                }
            }
        }
    }
}

// ---------------------------------------------------------------------------
// Kernel 2: tree traversal, 8 rows per block; path-index math computed once
// per leaf id and applied to all 8 rows.
// ---------------------------------------------------------------------------
#define RPB 8
__global__ __launch_bounds__(256)
void sdt_tree_kernel(const float* __restrict__ node_out,
                     const float* __restrict__ leaf,
                     float* __restrict__ h_out,
                     float* __restrict__ path_out,
                     float* __restrict__ reach_out) {
    const int b0 = blockIdx.x * RPB;
    const int t  = threadIdx.x;

    __shared__ float p[RPB][NUM_INNER];
    __shared__ float red[RPB][8];

    if (t < NUM_INNER) {
#pragma unroll
        for (int r = 0; r < RPB; r++)
            p[r][t] = node_out[(size_t)(b0 + r) * NUM_INNER + t];
    }
    __syncthreads();

    float prob[RPB];
#pragma unroll
    for (int r = 0; r < RPB; r++) prob[r] = 1.0f;

    int n = 0;
#pragma unroll
    for (int v = 0; v < DEPTH; v++) {
        if ((t & ((1 << (DEPTH - v)) - 1)) == 0) {
#pragma unroll
            for (int r = 0; r < RPB; r++)
                reach_out[(size_t)(b0 + r) * NUM_INNER + n] = prob[r];
        }
        int bit = (t >> (DEPTH - 1 - v)) & 1;
#pragma unroll
        for (int r = 0; r < RPB; r++) {
            float pv = p[r][n];
            prob[r] *= bit ? pv : (1.0f - pv);
        }
        n = 2 * n + 1 + bit;
    }

    const float lf = leaf[t];
#pragma unroll
    for (int r = 0; r < RPB; r++) {
        path_out[(size_t)(b0 + r) * NUM_LEAVES + t] = prob[r];
        float c = prob[r] * lf;
#pragma unroll
        for (int off = 16; off; off >>= 1)
            c += __shfl_xor_sync(0xffffffffu, c, off);
        if ((t & 31) == 0) red[r][t >> 5] = c;
    }
    __syncthreads();
    if (t < 64) {
        int r = t >> 3, i = t & 7;
        float v = red[r][i];
        v += __shfl_xor_sync(0xffffffffu, v, 4);
        v += __shfl_xor_sync(0xffffffffu, v, 2);
        v += __shfl_xor_sync(0xffffffffu, v, 1);
        if (i == 0) h_out[b0 + r] = v;
    }
}

// ---------------------------------------------------------------------------
// Launch. d_in: x, w1, b1, w2, b2, leaf.
// d_out: [h_out | path_probs | node_outputs | node_reach]
// ---------------------------------------------------------------------------
extern "C" void kernel_launch(void* const* d_in, const int* in_sizes, int n_in,
                              void* d_out, int out_size) {
    const float* x    = (const float*)d_in[0];
    const float* w1   = (const float*)d_in[1];
    const float* b1   = (const float*)d_in[2];
    const float* w2   = (const float*)d_in[3];
    const float* b2   = (const float*)d_in[4];
    const float* leaf = (const float*)d_in[5];

    float* out       = (float*)d_out;
    float* h_out     = out;
    float* path_out  = out + BATCH;
    float* node_out  = out + BATCH + (size_t)BATCH * NUM_LEAVES;
    float* reach_out = node_out + (size_t)BATCH * NUM_INNER;

    sdt_prep_kernel<<<2048, 256>>>(x, w1);

    cudaFuncSetAttribute(sdt_mma_kernel,
                         cudaFuncAttributeMaxDynamicSharedMemorySize, SMEM_TOTAL);
    dim3 grid(NODES_PAD / 2, BATCH / BM);   // 128 x 64
    sdt_mma_kernel<<<grid, 256, SMEM_TOTAL>>>(b1, w2, b2, node_out);

    sdt_tree_kernel<<<BATCH / RPB, 256>>>(node_out, leaf, h_out, path_out, reach_out);
}